// round 13
// baseline (speedup 1.0000x reference)
#include <cuda_runtime.h>
#include <cstdint>

// ---------------- scratch (device globals; zero-initialized, no alloc) -------
__device__ float g_k   [16LL * 1024 * 512];
__device__ float g_v   [16LL * 1024 * 512];
__device__ float g_q   [16LL * 2048 * 512];
__device__ float g_att [16LL * 2048 * 1024];
__device__ float g_vmel[16LL * 1024 * 1280];
__device__ int   g_len[16];

// -------- lengths dtype sniffing (reference says int64; JAX x64-off -> int32)
__global__ void normalize_lengths(const void* __restrict__ lp)
{
    const long long* l8 = (const long long*)lp;
    const int*       l4 = (const int*)lp;
    bool ok64 = true;
    for (int i = 0; i < 8; ++i) {
        long long v = l8[i];
        if (v < 1 || v > 1024) ok64 = false;
    }
    if (ok64) { for (int i = 0; i < 16; ++i) g_len[i] = (int)l8[i]; }
    else      { for (int i = 0; i < 16; ++i) g_len[i] = l4[i]; }
}

// ---------------------------------------------------------------------------
__device__ __forceinline__ unsigned f2tf(float x) {
    unsigned u; asm("cvt.rna.tf32.f32 %0, %1;" : "=r"(u) : "f"(x)); return u;
}
__device__ __forceinline__ void mma8(float* c, const unsigned* a,
                                     unsigned b0, unsigned b1) {
    asm volatile(
        "mma.sync.aligned.m16n8k8.row.col.f32.tf32.tf32.f32 "
        "{%0,%1,%2,%3},{%4,%5,%6,%7},{%8,%9},{%0,%1,%2,%3};"
        : "+f"(c[0]), "+f"(c[1]), "+f"(c[2]), "+f"(c[3])
        : "r"(a[0]), "r"(a[1]), "r"(a[2]), "r"(a[3]), "r"(b0), "r"(b1));
}
__device__ __forceinline__ void ldsm_x4(unsigned* r, unsigned addr) {
    asm volatile("ldmatrix.sync.aligned.m8n8.x4.shared.b16 {%0,%1,%2,%3}, [%4];"
        : "=r"(r[0]), "=r"(r[1]), "=r"(r[2]), "=r"(r[3]) : "r"(addr));
}
__device__ __forceinline__ void ldsm_x2(unsigned& r0, unsigned& r1, unsigned addr) {
    asm volatile("ldmatrix.sync.aligned.m8n8.x2.shared.b16 {%0,%1}, [%2];"
        : "=r"(r0), "=r"(r1) : "r"(addr));
}

// ---------------------------------------------------------------------------
// tf32 tensor-core GEMM, 128x128x16 CTA tiles, 128 threads (4 warps 2m x 2n),
// warp tile 64x64, m16n8k8. Double-buffered smem, LDG prefetch, 2 CTAs/SM.
// A smem is ALWAYS m-major As[m][20] (ldmatrix-friendly, conflict-free).
// AT=0: A row-major [M,K] (k contig, STS.128 fill).
// AT=1: A k-major  [K,M] (m contig source; 4x scalar STS fill, bank-clean).
// BT=0: B [K,N]  -> smem Bs[k][136], scalar frag loads.
// BT=1: B^T [N,K] -> smem Bs[n][20], ldmatrix.x2 frag loads.
// EPI=0: C = alpha*acc + bias[col] (bias optional); EPI=2: mel permute.
// LM: 0=none; 1=skip M-block when (r0&1023)>=len[r0>>10]; 2=skip CTA when
// c0>=len[z]; 3=clamp K iters to ceil(len[z]/16); 4=skip CTA when r0>=len[z].
template<int AT, int BT, int EPI, int LM>
__global__ __launch_bounds__(128, 2) void tc_gemm(
    const float* __restrict__ A, const float* __restrict__ Bm,
    const float* __restrict__ bias, float* __restrict__ C,
    int K, int lda, int ldb, int ldc,
    long long sA, long long sB, long long sC, float alpha)
{
    constexpr int ASZ = 128 * 20;
    constexpr int BSZ = BT ? 128 * 20 : 16 * 136;
    __shared__ unsigned smA[2][ASZ];
    __shared__ unsigned smB[2][BSZ];

    const int r0 = blockIdx.y * 128, c0 = blockIdx.x * 128;
    if (LM == 1) { if ((r0 & 1023) >= g_len[r0 >> 10]) return; }
    if (LM == 2) { if (c0 >= g_len[blockIdx.z]) return; }
    if (LM == 4) { if (r0 >= g_len[blockIdx.z]) return; }

    A  += blockIdx.z * sA;
    Bm += blockIdx.z * sB;
    const int tid  = threadIdx.x;
    const int lane = tid & 31, warp = tid >> 5;
    const int wm = warp & 1,  wn = warp >> 1;

    // ldmatrix lane-addressed bases (bytes)
    const unsigned smA_u = (unsigned)__cvta_generic_to_shared(&smA[0][0]);
    const unsigned smB_u = (unsigned)__cvta_generic_to_shared(&smB[0][0]);
    const int rowA = wm * 64 + (lane & 7) + ((lane >> 3) & 1) * 8;
    const unsigned aoff = (unsigned)(rowA * 20 + (lane >> 4) * 4) * 4u;
    const int rowB = wn * 64 + (lane & 7);
    const unsigned boff = (unsigned)(rowB * 20 + ((lane >> 3) & 1) * 4) * 4u;

    const float* aptr[4]; unsigned adst[4];
    const float* bptr[4]; unsigned bdst[4];
    #pragma unroll
    for (int r = 0; r < 4; ++r) {
        int i = tid + 128 * r;
        if (!AT) { int m = i >> 2, kq = (i & 3) * 4;
                   aptr[r] = A + (long long)(r0 + m) * lda + kq;
                   adst[r] = m * 20 + kq; }
        else     { int k = i & 15, m4 = (i >> 4) * 4;
                   aptr[r] = A + (long long)k * lda + r0 + m4;
                   adst[r] = m4 * 20 + k; }
        if (!BT) { int k = i >> 5, n4 = (i & 31) * 4;
                   bptr[r] = Bm + (long long)k * ldb + c0 + n4;
                   bdst[r] = k * 136 + n4; }
        else     { int n = i >> 2, kq = (i & 3) * 4;
                   bptr[r] = Bm + (long long)(c0 + n) * ldb + kq;
                   bdst[r] = n * 20 + kq; }
    }
    const long long adv_a = AT ? 16LL * lda : 16LL;
    const long long adv_b = BT ? 16LL : 16LL * ldb;

    float acc[4][8][4] = {};
    int nIter = K >> 4;
    if (LM == 3) {
        int nl = (g_len[blockIdx.z] + 15) >> 4;
        if (nl < nIter) nIter = nl;
    }

    float4 pa[4], pb[4];
    #pragma unroll
    for (int r = 0; r < 4; ++r) {
        pa[r] = *(const float4*)aptr[r];
        pb[r] = *(const float4*)bptr[r];
    }

    int buf = 0;
    for (int it = 0; it < nIter; ++it) {
        #pragma unroll
        for (int r = 0; r < 4; ++r) {
            if (!AT) {
                uint4 ua; ua.x = f2tf(pa[r].x); ua.y = f2tf(pa[r].y);
                          ua.z = f2tf(pa[r].z); ua.w = f2tf(pa[r].w);
                *(uint4*)&smA[buf][adst[r]] = ua;
            } else {
                smA[buf][adst[r] +  0] = f2tf(pa[r].x);
                smA[buf][adst[r] + 20] = f2tf(pa[r].y);
                smA[buf][adst[r] + 40] = f2tf(pa[r].z);
                smA[buf][adst[r] + 60] = f2tf(pa[r].w);
            }
            uint4 ub; ub.x = f2tf(pb[r].x); ub.y = f2tf(pb[r].y);
                      ub.z = f2tf(pb[r].z); ub.w = f2tf(pb[r].w);
            *(uint4*)&smB[buf][bdst[r]] = ub;
        }
        if (it + 1 < nIter) {
            #pragma unroll
            for (int r = 0; r < 4; ++r) {
                aptr[r] += adv_a; bptr[r] += adv_b;
                pa[r] = *(const float4*)aptr[r];
                pb[r] = *(const float4*)bptr[r];
            }
        }
        __syncthreads();
        const unsigned abase = smA_u + (unsigned)buf * (ASZ * 4u) + aoff;
        const unsigned bbase = smB_u + (unsigned)buf * (BSZ * 4u) + boff;
        const unsigned* Bs = smB[buf];
        #pragma unroll
        for (int kk = 0; kk < 16; kk += 8) {
            unsigned af[4][4];
            #pragma unroll
            for (int mi = 0; mi < 4; ++mi)
                ldsm_x4(af[mi], abase + (unsigned)(mi * 1280 + kk * 4));
            #pragma unroll
            for (int ni = 0; ni < 8; ++ni) {
                unsigned b0, b1;
                if (BT) {
                    ldsm_x2(b0, b1, bbase + (unsigned)(ni * 640 + kk * 4));
                } else {
                    const int k = kk + (lane & 3);
                    const int n = wn * 64 + ni * 8 + (lane >> 2);
                    b0 = Bs[k * 136 + n];
                    b1 = Bs[(k + 4) * 136 + n];
                }
                #pragma unroll
                for (int mi = 0; mi < 4; ++mi)
                    mma8(acc[mi][ni], af[mi], b0, b1);
            }
        }
        buf ^= 1;
    }

    const int g = lane >> 2, tg = lane & 3;
    if (EPI == 2) {
        const int b = blockIdx.z;
        #pragma unroll
        for (int mi = 0; mi < 4; ++mi) {
            int row = r0 + wm * 64 + mi * 16 + g;
            #pragma unroll
            for (int rr = 0; rr < 2; ++rr) {
                int mel = row + rr * 8;
                float bb = bias[mel];
                float* op = C + ((long long)(b * 64 + (mel & 63)) * 20 + (mel >> 6)) * 2048;
                #pragma unroll
                for (int ni = 0; ni < 8; ++ni) {
                    int t = c0 + wn * 64 + ni * 8 + 2 * tg;
                    float2 v;
                    v.x = acc[mi][ni][rr * 2 + 0] + bb;
                    v.y = acc[mi][ni][rr * 2 + 1] + bb;
                    *(float2*)(op + t) = v;
                }
            }
        }
    } else {
        C += blockIdx.z * sC;
        #pragma unroll
        for (int mi = 0; mi < 4; ++mi) {
            int row = r0 + wm * 64 + mi * 16 + g;
            #pragma unroll
            for (int ni = 0; ni < 8; ++ni) {
                int col = c0 + wn * 64 + ni * 8 + 2 * tg;
                float b0v = bias ? bias[col] : 0.f;
                float b1v = bias ? bias[col + 1] : 0.f;
                float2 v0, v1;
                v0.x = alpha * acc[mi][ni][0] + b0v;
                v0.y = alpha * acc[mi][ni][1] + b1v;
                v1.x = alpha * acc[mi][ni][2] + b0v;
                v1.y = alpha * acc[mi][ni][3] + b1v;
                *(float2*)(C + (long long)row * ldc + col)       = v0;
                *(float2*)(C + (long long)(row + 8) * ldc + col) = v1;
            }
        }
    }
}

// -------- masked softmax over S=1024 per (b,t) row, length-clamped -----------
__global__ __launch_bounds__(256) void softmax_rows(float* __restrict__ att)
{
    const int row = blockIdx.x;
    const int b = row >> 11;
    float* p = att + (long long)row * 1024;
    const int len = g_len[b];
    const int lim = (len + 15) & ~15;
    const int tid = threadIdx.x;
    const int s0 = tid * 4;
    const bool act = s0 < lim;
    float4 v = make_float4(0.f, 0.f, 0.f, 0.f);
    if (act) v = ((const float4*)p)[tid];
    float vals[4] = {v.x, v.y, v.z, v.w};
    float mx = -1e30f;
    #pragma unroll
    for (int u = 0; u < 4; ++u)
        if (s0 + u < len && vals[u] > mx) mx = vals[u];
    __shared__ float red[8];
    #pragma unroll
    for (int off = 16; off > 0; off >>= 1)
        mx = fmaxf(mx, __shfl_xor_sync(0xffffffffu, mx, off));
    if ((tid & 31) == 0) red[tid >> 5] = mx;
    __syncthreads();
    mx = red[0];
    #pragma unroll
    for (int i = 1; i < 8; ++i) mx = fmaxf(mx, red[i]);
    __syncthreads();
    float sum = 0.f;
    #pragma unroll
    for (int u = 0; u < 4; ++u) {
        float e = (s0 + u < len) ? __expf(vals[u] - mx) : 0.f;
        vals[u] = e; sum += e;
    }
    #pragma unroll
    for (int off = 16; off > 0; off >>= 1)
        sum += __shfl_xor_sync(0xffffffffu, sum, off);
    if ((tid & 31) == 0) red[tid >> 5] = sum;
    __syncthreads();
    sum = 0.f;
    #pragma unroll
    for (int i = 0; i < 8; ++i) sum += red[i];
    const float inv = 1.f / sum;
    if (act) {
        v.x = vals[0] * inv; v.y = vals[1] * inv;
        v.z = vals[2] * inv; v.w = vals[3] * inv;
        ((float4*)p)[tid] = v;
    }
}

// ---------------------------------------------------------------------------
extern "C" void kernel_launch(void* const* d_in, const int* in_sizes, int n_in,
                              void* d_out, int out_size)
{
    const float* ph      = (const float*)d_in[0];
    const float* g       = (const float*)d_in[1];
    const void*  lengths = d_in[2];
    const float* Wk      = (const float*)d_in[3];
    const float* bk      = (const float*)d_in[4];
    const float* Wv      = (const float*)d_in[5];
    const float* bv      = (const float*)d_in[6];
    const float* Wq      = (const float*)d_in[7];
    const float* bq      = (const float*)d_in[8];
    const float* Wmel    = (const float*)d_in[9];
    const float* bmel    = (const float*)d_in[10];
    float* out = (float*)d_out;

    float *k_, *v_, *q_, *att_, *vmel_;
    cudaGetSymbolAddress((void**)&k_,    g_k);
    cudaGetSymbolAddress((void**)&v_,    g_v);
    cudaGetSymbolAddress((void**)&q_,    g_q);
    cudaGetSymbolAddress((void**)&att_,  g_att);
    cudaGetSymbolAddress((void**)&vmel_, g_vmel);

    const dim3 th(128);

    normalize_lengths<<<1, 1>>>(lengths);

    // k = ph@Wk + bk ; v = ph@Wv + bv  (skip s-blocks >= len[b])
    tc_gemm<0,0,0,1><<<dim3(4, 128, 1), th>>>(ph, Wk, bk, k_,
        512, 512, 512, 512, 0, 0, 0, 1.f);
    tc_gemm<0,0,0,1><<<dim3(4, 128, 1), th>>>(ph, Wv, bv, v_,
        512, 512, 512, 512, 0, 0, 0, 1.f);

    // q = g^T@Wq + bq  (A k-major per batch)
    tc_gemm<1,0,0,0><<<dim3(4, 16, 16), th>>>(g, Wq, bq, q_,
        2560, 2048, 512, 512, 2560LL * 2048, 0, 2048LL * 512, 1.f);

    // att = scale * q@k^T  (skip CTAs with c0 >= len[b])
    tc_gemm<0,1,0,2><<<dim3(8, 16, 16), th>>>(q_, k_, nullptr, att_,
        512, 512, 512, 1024, 2048LL * 512, 1024LL * 512, 2048LL * 1024,
        0.04419417382415922f);

    softmax_rows<<<32768, 256>>>(att_);

    // vmel = v@Wmel  (per batch [1024,1280]; skip s-blocks >= len[b])
    tc_gemm<0,0,0,4><<<dim3(10, 8, 16), th>>>(v_, Wmel, nullptr, vmel_,
        512, 512, 1280, 1280, 1024LL * 512, 0, 1024LL * 1280, 1.f);

    // out = permute(att@vmel + bmel): rows=mel (A=vmel k-major), cols=t
    // (B=att row-major, BT=1), K=S clamped to ceil(len/16)*16
    tc_gemm<1,1,2,3><<<dim3(16, 10, 16), th>>>(vmel_, att_, bmel, out,
        1024, 1280, 1024, 2048, 1024LL * 1280, 2048LL * 1024, 0, 1.f);
}

// round 15
// speedup vs baseline: 1.3734x; 1.3734x over previous
#include <cuda_runtime.h>
#include <cstdint>

// ---------------- scratch (device globals; zero-initialized, no alloc) -------
__device__ float g_k   [16LL * 1024 * 512];
__device__ float g_v   [16LL * 1024 * 512];
__device__ float g_q   [16LL * 2048 * 512];
__device__ float g_att [16LL * 2048 * 1024];
__device__ float g_vmel[16LL * 1024 * 1280];
__device__ float g_phc [16LL * 1024 * 512];
__device__ float g_wkc [512 * 512];
__device__ float g_wvc [512 * 512];
__device__ float g_wqc [2560LL * 512];
__device__ float g_wmc [512LL * 1280];
__device__ int   g_len[16];

// -------- lengths dtype sniffing (reference says int64; JAX x64-off -> int32)
__global__ void normalize_lengths(const void* __restrict__ lp)
{
    const long long* l8 = (const long long*)lp;
    const int*       l4 = (const int*)lp;
    bool ok64 = true;
    for (int i = 0; i < 8; ++i) {
        long long v = l8[i];
        if (v < 1 || v > 1024) ok64 = false;
    }
    if (ok64) { for (int i = 0; i < 16; ++i) g_len[i] = (int)l8[i]; }
    else      { for (int i = 0; i < 16; ++i) g_len[i] = l4[i]; }
}

// ---------------------------------------------------------------------------
__device__ __forceinline__ unsigned f2tf(float x) {
    unsigned u; asm("cvt.rna.tf32.f32 %0, %1;" : "=r"(u) : "f"(x)); return u;
}
__device__ __forceinline__ void mma8(float* c, const unsigned* a,
                                     unsigned b0, unsigned b1) {
    asm volatile(
        "mma.sync.aligned.m16n8k8.row.col.f32.tf32.tf32.f32 "
        "{%0,%1,%2,%3},{%4,%5,%6,%7},{%8,%9},{%0,%1,%2,%3};"
        : "+f"(c[0]), "+f"(c[1]), "+f"(c[2]), "+f"(c[3])
        : "r"(a[0]), "r"(a[1]), "r"(a[2]), "r"(a[3]), "r"(b0), "r"(b1));
}

// -------- one-time tf32 pre-round of raw inputs ------------------------------
__global__ __launch_bounds__(256) void cvt_copy(
    const float4* __restrict__ src, float4* __restrict__ dst, int n4)
{
    int i = blockIdx.x * 256 + threadIdx.x;
    if (i >= n4) return;
    float4 v = src[i];
    uint4 u; u.x = f2tf(v.x); u.y = f2tf(v.y); u.z = f2tf(v.z); u.w = f2tf(v.w);
    dst[i] = *(float4*)&u;
}

// ---------------------------------------------------------------------------
// tf32 tensor-core GEMM, 128x128x16 CTA tiles, 128 threads (4 warps 2m x 2n),
// warp tile 64x64, m16n8k8. Double-buffered smem, LDG register prefetch,
// 2 CTAs/SM.  (R11 loop structure — race-free; no cp.async.)
// AT=0: A row-major [M,K] -> smem As[m][20]; AT=1: A k-major [K,M] -> As[k][136].
// BT=0: B [K,N] -> Bs[k][136]; BT=1: B^T [N,K] -> Bs[n][20].
// CA/CB: 1 = operand already tf32-rounded in gmem -> fill skips cvt (f2tf is
// idempotent, so this is bit-identical to converting at fill time).
// EPI=0: C = alpha*acc + bias[col] (bias optional); EPI=2: mel permute.
// OT=1: epilogue stores tf32-rounded bits (output consumed only by GEMMs).
// LM: 0=none; 1=skip M-block when (r0&1023)>=len[r0>>10]; 2=skip CTA when
// c0>=len[z]; 3=clamp K iters to ceil(len[z]/16); 4=skip CTA when r0>=len[z].
template<int AT, int BT, int EPI, int LM, int CA, int CB, int OT>
__global__ __launch_bounds__(128, 2) void tc_gemm(
    const float* __restrict__ A, const float* __restrict__ Bm,
    const float* __restrict__ bias, float* __restrict__ C,
    int K, int lda, int ldb, int ldc,
    long long sA, long long sB, long long sC, float alpha)
{
    constexpr int ASZ = AT ? 16 * 136 : 128 * 20;
    constexpr int BSZ = BT ? 128 * 20 : 16 * 136;
    __shared__ unsigned smA[2][ASZ];
    __shared__ unsigned smB[2][BSZ];

    const int r0 = blockIdx.y * 128, c0 = blockIdx.x * 128;
    if (LM == 1) { if ((r0 & 1023) >= g_len[r0 >> 10]) return; }
    if (LM == 2) { if (c0 >= g_len[blockIdx.z]) return; }
    if (LM == 4) { if (r0 >= g_len[blockIdx.z]) return; }

    A  += blockIdx.z * sA;
    Bm += blockIdx.z * sB;
    const int tid  = threadIdx.x;
    const int lane = tid & 31, warp = tid >> 5;
    const int g  = lane >> 2, tg = lane & 3;
    const int wm = warp & 1,  wn = warp >> 1;

    const float* aptr[4]; unsigned adst[4];
    const float* bptr[4]; unsigned bdst[4];
    #pragma unroll
    for (int r = 0; r < 4; ++r) {
        int i = tid + 128 * r;
        if (!AT) { int m = i >> 2, kq = (i & 3) * 4;
                   aptr[r] = A + (long long)(r0 + m) * lda + kq;
                   adst[r] = m * 20 + kq; }
        else     { int k = i >> 5, m4 = (i & 31) * 4;
                   aptr[r] = A + (long long)k * lda + r0 + m4;
                   adst[r] = k * 136 + m4; }
        if (!BT) { int k = i >> 5, n4 = (i & 31) * 4;
                   bptr[r] = Bm + (long long)k * ldb + c0 + n4;
                   bdst[r] = k * 136 + n4; }
        else     { int n = i >> 2, kq = (i & 3) * 4;
                   bptr[r] = Bm + (long long)(c0 + n) * ldb + kq;
                   bdst[r] = n * 20 + kq; }
    }
    const long long adv_a = AT ? 16LL * lda : 16LL;
    const long long adv_b = BT ? 16LL : 16LL * ldb;

    float acc[4][8][4] = {};
    int nIter = K >> 4;
    if (LM == 3) {
        int nl = (g_len[blockIdx.z] + 15) >> 4;
        if (nl < nIter) nIter = nl;
    }

    float4 pa[4], pb[4];
    #pragma unroll
    for (int r = 0; r < 4; ++r) {
        pa[r] = *(const float4*)aptr[r];
        pb[r] = *(const float4*)bptr[r];
    }

    int buf = 0;
    for (int it = 0; it < nIter; ++it) {
        #pragma unroll
        for (int r = 0; r < 4; ++r) {
            if (CA) {
                *(uint4*)&smA[buf][adst[r]] = *(uint4*)&pa[r];
            } else {
                uint4 ua; ua.x = f2tf(pa[r].x); ua.y = f2tf(pa[r].y);
                          ua.z = f2tf(pa[r].z); ua.w = f2tf(pa[r].w);
                *(uint4*)&smA[buf][adst[r]] = ua;
            }
            if (CB) {
                *(uint4*)&smB[buf][bdst[r]] = *(uint4*)&pb[r];
            } else {
                uint4 ub; ub.x = f2tf(pb[r].x); ub.y = f2tf(pb[r].y);
                          ub.z = f2tf(pb[r].z); ub.w = f2tf(pb[r].w);
                *(uint4*)&smB[buf][bdst[r]] = ub;
            }
        }
        if (it + 1 < nIter) {
            #pragma unroll
            for (int r = 0; r < 4; ++r) {
                aptr[r] += adv_a; bptr[r] += adv_b;
                pa[r] = *(const float4*)aptr[r];
                pb[r] = *(const float4*)bptr[r];
            }
        }
        __syncthreads();
        const unsigned* As = smA[buf];
        const unsigned* Bs = smB[buf];
        #pragma unroll
        for (int kk = 0; kk < 16; kk += 8) {
            unsigned af[4][4];
            const int k = kk + tg;
            #pragma unroll
            for (int mi = 0; mi < 4; ++mi) {
                int m = wm * 64 + mi * 16 + g;
                if (!AT) {
                    af[mi][0] = As[m * 20 + k];
                    af[mi][1] = As[(m + 8) * 20 + k];
                    af[mi][2] = As[m * 20 + k + 4];
                    af[mi][3] = As[(m + 8) * 20 + k + 4];
                } else {
                    af[mi][0] = As[k * 136 + m];
                    af[mi][1] = As[k * 136 + m + 8];
                    af[mi][2] = As[(k + 4) * 136 + m];
                    af[mi][3] = As[(k + 4) * 136 + m + 8];
                }
            }
            #pragma unroll
            for (int ni = 0; ni < 8; ++ni) {
                int n = wn * 64 + ni * 8 + g;
                unsigned b0, b1;
                if (!BT) { b0 = Bs[k * 136 + n]; b1 = Bs[(k + 4) * 136 + n]; }
                else     { b0 = Bs[n * 20 + k];  b1 = Bs[n * 20 + k + 4]; }
                #pragma unroll
                for (int mi = 0; mi < 4; ++mi)
                    mma8(acc[mi][ni], af[mi], b0, b1);
            }
        }
        buf ^= 1;
    }

    if (EPI == 2) {
        const int b = blockIdx.z;
        #pragma unroll
        for (int mi = 0; mi < 4; ++mi) {
            int row = r0 + wm * 64 + mi * 16 + g;
            #pragma unroll
            for (int rr = 0; rr < 2; ++rr) {
                int mel = row + rr * 8;
                float bb = bias[mel];
                float* op = C + ((long long)(b * 64 + (mel & 63)) * 20 + (mel >> 6)) * 2048;
                #pragma unroll
                for (int ni = 0; ni < 8; ++ni) {
                    int t = c0 + wn * 64 + ni * 8 + 2 * tg;
                    float2 v;
                    v.x = acc[mi][ni][rr * 2 + 0] + bb;
                    v.y = acc[mi][ni][rr * 2 + 1] + bb;
                    *(float2*)(op + t) = v;
                }
            }
        }
    } else {
        C += blockIdx.z * sC;
        #pragma unroll
        for (int mi = 0; mi < 4; ++mi) {
            int row = r0 + wm * 64 + mi * 16 + g;
            #pragma unroll
            for (int ni = 0; ni < 8; ++ni) {
                int col = c0 + wn * 64 + ni * 8 + 2 * tg;
                float b0v = bias ? bias[col] : 0.f;
                float b1v = bias ? bias[col + 1] : 0.f;
                float o0 = alpha * acc[mi][ni][0] + b0v;
                float o1 = alpha * acc[mi][ni][1] + b1v;
                float o2 = alpha * acc[mi][ni][2] + b0v;
                float o3 = alpha * acc[mi][ni][3] + b1v;
                float2 v0, v1;
                if (OT) {
                    v0.x = __uint_as_float(f2tf(o0));
                    v0.y = __uint_as_float(f2tf(o1));
                    v1.x = __uint_as_float(f2tf(o2));
                    v1.y = __uint_as_float(f2tf(o3));
                } else { v0.x = o0; v0.y = o1; v1.x = o2; v1.y = o3; }
                *(float2*)(C + (long long)row * ldc + col)       = v0;
                *(float2*)(C + (long long)(row + 8) * ldc + col) = v1;
            }
        }
    }
}

// -------- masked softmax, length-clamped; stores tf32-rounded weights --------
__global__ __launch_bounds__(256) void softmax_rows(float* __restrict__ att)
{
    const int row = blockIdx.x;
    const int b = row >> 11;
    float* p = att + (long long)row * 1024;
    const int len = g_len[b];
    const int lim = (len + 15) & ~15;
    const int tid = threadIdx.x;
    const int s0 = tid * 4;
    const bool act = s0 < lim;
    float4 v = make_float4(0.f, 0.f, 0.f, 0.f);
    if (act) v = ((const float4*)p)[tid];
    float vals[4] = {v.x, v.y, v.z, v.w};
    float mx = -1e30f;
    #pragma unroll
    for (int u = 0; u < 4; ++u)
        if (s0 + u < len && vals[u] > mx) mx = vals[u];
    __shared__ float red[8];
    #pragma unroll
    for (int off = 16; off > 0; off >>= 1)
        mx = fmaxf(mx, __shfl_xor_sync(0xffffffffu, mx, off));
    if ((tid & 31) == 0) red[tid >> 5] = mx;
    __syncthreads();
    mx = red[0];
    #pragma unroll
    for (int i = 1; i < 8; ++i) mx = fmaxf(mx, red[i]);
    __syncthreads();
    float sum = 0.f;
    #pragma unroll
    for (int u = 0; u < 4; ++u) {
        float e = (s0 + u < len) ? __expf(vals[u] - mx) : 0.f;
        vals[u] = e; sum += e;
    }
    #pragma unroll
    for (int off = 16; off > 0; off >>= 1)
        sum += __shfl_xor_sync(0xffffffffu, sum, off);
    if ((tid & 31) == 0) red[tid >> 5] = sum;
    __syncthreads();
    sum = 0.f;
    #pragma unroll
    for (int i = 0; i < 8; ++i) sum += red[i];
    const float inv = 1.f / sum;
    if (act) {
        v.x = __uint_as_float(f2tf(vals[0] * inv));
        v.y = __uint_as_float(f2tf(vals[1] * inv));
        v.z = __uint_as_float(f2tf(vals[2] * inv));
        v.w = __uint_as_float(f2tf(vals[3] * inv));
        ((float4*)p)[tid] = v;
    }
}

// ---------------------------------------------------------------------------
extern "C" void kernel_launch(void* const* d_in, const int* in_sizes, int n_in,
                              void* d_out, int out_size)
{
    const float* ph      = (const float*)d_in[0];
    const float* g       = (const float*)d_in[1];
    const void*  lengths = d_in[2];
    const float* Wk      = (const float*)d_in[3];
    const float* bk      = (const float*)d_in[4];
    const float* Wv      = (const float*)d_in[5];
    const float* bv      = (const float*)d_in[6];
    const float* Wq      = (const float*)d_in[7];
    const float* bq      = (const float*)d_in[8];
    const float* Wmel    = (const float*)d_in[9];
    const float* bmel    = (const float*)d_in[10];
    float* out = (float*)d_out;

    float *k_, *v_, *q_, *att_, *vmel_, *phc_, *wkc_, *wvc_, *wqc_, *wmc_;
    cudaGetSymbolAddress((void**)&k_,    g_k);
    cudaGetSymbolAddress((void**)&v_,    g_v);
    cudaGetSymbolAddress((void**)&q_,    g_q);
    cudaGetSymbolAddress((void**)&att_,  g_att);
    cudaGetSymbolAddress((void**)&vmel_, g_vmel);
    cudaGetSymbolAddress((void**)&phc_,  g_phc);
    cudaGetSymbolAddress((void**)&wkc_,  g_wkc);
    cudaGetSymbolAddress((void**)&wvc_,  g_wvc);
    cudaGetSymbolAddress((void**)&wqc_,  g_wqc);
    cudaGetSymbolAddress((void**)&wmc_,  g_wmc);

    const dim3 th(128);

    normalize_lengths<<<1, 1>>>(lengths);

    // pre-round raw inputs (except g) to tf32 bits — bit-identical to
    // converting at fill time, since cvt.rna is idempotent.
    cvt_copy<<<8192, 256>>>((const float4*)ph,   (float4*)phc_, 2097152);
    cvt_copy<<<256,  256>>>((const float4*)Wk,   (float4*)wkc_, 65536);
    cvt_copy<<<256,  256>>>((const float4*)Wv,   (float4*)wvc_, 65536);
    cvt_copy<<<1280, 256>>>((const float4*)Wq,   (float4*)wqc_, 327680);
    cvt_copy<<<640,  256>>>((const float4*)Wmel, (float4*)wmc_, 163840);

    // k = ph@Wk + bk ; v = ph@Wv + bv  (skip s-blocks >= len[b]; no fill cvt)
    tc_gemm<0,0,0,1,1,1,1><<<dim3(4, 128, 1), th>>>(phc_, wkc_, bk, k_,
        512, 512, 512, 512, 0, 0, 0, 1.f);
    tc_gemm<0,0,0,1,1,1,1><<<dim3(4, 128, 1), th>>>(phc_, wvc_, bv, v_,
        512, 512, 512, 512, 0, 0, 0, 1.f);

    // q = g^T@Wq + bq  (A = g raw k-major -> cvt fill; B pre-rounded)
    tc_gemm<1,0,0,0,0,1,1><<<dim3(4, 16, 16), th>>>(g, wqc_, bq, q_,
        2560, 2048, 512, 512, 2560LL * 2048, 0, 2048LL * 512, 1.f);

    // att = scale * q@k^T  (skip CTAs with c0 >= len[b]; both pre-rounded)
    tc_gemm<0,1,0,2,1,1,0><<<dim3(8, 16, 16), th>>>(q_, k_, nullptr, att_,
        512, 512, 512, 1024, 2048LL * 512, 1024LL * 512, 2048LL * 1024,
        0.04419417382415922f);

    softmax_rows<<<32768, 256>>>(att_);

    // vmel = v@Wmel  (skip s-blocks >= len[b]; both pre-rounded)
    tc_gemm<0,0,0,4,1,1,1><<<dim3(10, 8, 16), th>>>(v_, wmc_, nullptr, vmel_,
        512, 512, 1280, 1280, 1024LL * 512, 0, 1024LL * 1280, 1.f);

    // out = permute(att@vmel + bmel): rows=mel (A=vmel k-major), cols=t,
    // K=S clamped to ceil(len/16)*16; both operands pre-rounded
    tc_gemm<1,1,2,3,1,1,0><<<dim3(16, 10, 16), th>>>(vmel_, att_, bmel, out,
        1024, 1280, 1024, 2048, 1024LL * 1280, 2048LL * 1024, 0, 1.f);
}

// round 16
// speedup vs baseline: 1.4378x; 1.0468x over previous
#include <cuda_runtime.h>
#include <cstdint>

// ---------------- scratch (device globals; zero-initialized, no alloc) -------
__device__ float g_k   [16LL * 1024 * 512];
__device__ float g_v   [16LL * 1024 * 512];
__device__ float g_q   [16LL * 2048 * 512];
__device__ float g_att [16LL * 2048 * 1024];
__device__ float g_vmel[16LL * 1024 * 1280];
__device__ float g_phc [16LL * 1024 * 512];
__device__ float g_wkc [512 * 512];
__device__ float g_wvc [512 * 512];
__device__ float g_wqc [2560LL * 512];
__device__ float g_wmc [512LL * 1280];
__device__ int   g_len[16];

// -------- lengths dtype sniffing (reference says int64; JAX x64-off -> int32)
__global__ void normalize_lengths(const void* __restrict__ lp)
{
    const long long* l8 = (const long long*)lp;
    const int*       l4 = (const int*)lp;
    bool ok64 = true;
    for (int i = 0; i < 8; ++i) {
        long long v = l8[i];
        if (v < 1 || v > 1024) ok64 = false;
    }
    if (ok64) { for (int i = 0; i < 16; ++i) g_len[i] = (int)l8[i]; }
    else      { for (int i = 0; i < 16; ++i) g_len[i] = l4[i]; }
}

// ---------------------------------------------------------------------------
__device__ __forceinline__ unsigned f2tf(float x) {
    unsigned u; asm("cvt.rna.tf32.f32 %0, %1;" : "=r"(u) : "f"(x)); return u;
}
__device__ __forceinline__ void mma8(float* c, const unsigned* a,
                                     unsigned b0, unsigned b1) {
    asm volatile(
        "mma.sync.aligned.m16n8k8.row.col.f32.tf32.tf32.f32 "
        "{%0,%1,%2,%3},{%4,%5,%6,%7},{%8,%9},{%0,%1,%2,%3};"
        : "+f"(c[0]), "+f"(c[1]), "+f"(c[2]), "+f"(c[3])
        : "r"(a[0]), "r"(a[1]), "r"(a[2]), "r"(a[3]), "r"(b0), "r"(b1));
}
__device__ __forceinline__ void cp16(unsigned dst, const void* src) {
    asm volatile("cp.async.cg.shared.global [%0], [%1], 16;"
                 :: "r"(dst), "l"(src) : "memory");
}
#define CP_COMMIT() asm volatile("cp.async.commit_group;" ::: "memory")
#define CP_WAIT1()  asm volatile("cp.async.wait_group 1;" ::: "memory")

// -------- one-time tf32 pre-round of raw inputs ------------------------------
__global__ __launch_bounds__(256) void cvt_copy(
    const float4* __restrict__ src, float4* __restrict__ dst, int n4)
{
    int i = blockIdx.x * 256 + threadIdx.x;
    if (i >= n4) return;
    float4 v = src[i];
    uint4 u; u.x = f2tf(v.x); u.y = f2tf(v.y); u.z = f2tf(v.z); u.w = f2tf(v.w);
    dst[i] = *(float4*)&u;
}

// ---------------------------------------------------------------------------
// tf32 tensor-core GEMM, 128x128x16 CTA tiles, 128 threads (4 warps 2m x 2n),
// warp tile 64x64, m16n8k8. 3-stage cp.async pipeline (one barrier per iter;
// stage it+2 issued AFTER barrier it, so its buffer — last read at it-1 — is
// provably drained). Operands are tf32 bits in gmem (pre-rounded), except g
// which the MMA truncates. 2 CTAs/SM.
// AT=0: A row-major [M,K] -> smem As[m][20]; AT=1: A k-major [K,M] -> As[k][136].
// BT=0: B [K,N] -> Bs[k][136]; BT=1: B^T [N,K] -> Bs[n][20].
// EPI=0: C = alpha*acc + bias[col] (bias optional); EPI=2: mel permute.
// OT=1: epilogue stores tf32-rounded bits (output consumed only by GEMMs).
// LM: 0=none; 1=skip M-block when (r0&1023)>=len[r0>>10]; 2=skip CTA when
// c0>=len[z]; 3=clamp K iters to ceil(len[z]/16); 4=skip CTA when r0>=len[z].
template<int AT, int BT, int EPI, int LM, int OT>
__global__ __launch_bounds__(128, 2) void tc_gemm(
    const float* __restrict__ A, const float* __restrict__ Bm,
    const float* __restrict__ bias, float* __restrict__ C,
    int K, int lda, int ldb, int ldc,
    long long sA, long long sB, long long sC, float alpha)
{
    constexpr int ASZ = AT ? 16 * 136 : 128 * 20;
    constexpr int BSZ = BT ? 128 * 20 : 16 * 136;
    __shared__ __align__(16) unsigned smA[3][ASZ];
    __shared__ __align__(16) unsigned smB[3][BSZ];

    const int r0 = blockIdx.y * 128, c0 = blockIdx.x * 128;
    if (LM == 1) { if ((r0 & 1023) >= g_len[r0 >> 10]) return; }
    if (LM == 2) { if (c0 >= g_len[blockIdx.z]) return; }
    if (LM == 4) { if (r0 >= g_len[blockIdx.z]) return; }

    A  += blockIdx.z * sA;
    Bm += blockIdx.z * sB;
    const int tid  = threadIdx.x;
    const int lane = tid & 31, warp = tid >> 5;
    const int g  = lane >> 2, tg = lane & 3;
    const int wm = warp & 1,  wn = warp >> 1;

    const unsigned smA_u = (unsigned)__cvta_generic_to_shared(&smA[0][0]);
    const unsigned smB_u = (unsigned)__cvta_generic_to_shared(&smB[0][0]);

    const float* aptr[4]; unsigned adst[4];
    const float* bptr[4]; unsigned bdst[4];
    #pragma unroll
    for (int r = 0; r < 4; ++r) {
        int i = tid + 128 * r;
        if (!AT) { int m = i >> 2, kq = (i & 3) * 4;
                   aptr[r] = A + (long long)(r0 + m) * lda + kq;
                   adst[r] = (m * 20 + kq) * 4u; }
        else     { int k = i >> 5, m4 = (i & 31) * 4;
                   aptr[r] = A + (long long)k * lda + r0 + m4;
                   adst[r] = (k * 136 + m4) * 4u; }
        if (!BT) { int k = i >> 5, n4 = (i & 31) * 4;
                   bptr[r] = Bm + (long long)k * ldb + c0 + n4;
                   bdst[r] = (k * 136 + n4) * 4u; }
        else     { int n = i >> 2, kq = (i & 3) * 4;
                   bptr[r] = Bm + (long long)(c0 + n) * ldb + kq;
                   bdst[r] = (n * 20 + kq) * 4u; }
    }
    const long long adv_a = AT ? 16LL * lda : 16LL;
    const long long adv_b = BT ? 16LL : 16LL * ldb;

    float acc[4][8][4] = {};
    int nIter = K >> 4;
    if (LM == 3) {
        int nl = (g_len[blockIdx.z] + 15) >> 4;
        if (nl < nIter) nIter = nl;
    }

    // prologue: issue stages 0 and 1 (commit a group each, empty if absent)
    #pragma unroll
    for (int s = 0; s < 2; ++s) {
        if (s < nIter) {
            #pragma unroll
            for (int r = 0; r < 4; ++r) {
                cp16(smA_u + (unsigned)s * (ASZ * 4u) + adst[r], aptr[r]);
                cp16(smB_u + (unsigned)s * (BSZ * 4u) + bdst[r], bptr[r]);
                aptr[r] += adv_a; bptr[r] += adv_b;
            }
        }
        CP_COMMIT();
    }

    int cb = 0, nb = 2;   // compute buffer = it%3, issue buffer = (it+2)%3
    for (int it = 0; it < nIter; ++it) {
        CP_WAIT1();          // stage it landed (<=1 group still in flight)
        __syncthreads();     // visible to all; buffer nb drained (read at it-1)
        if (it + 2 < nIter) {
            #pragma unroll
            for (int r = 0; r < 4; ++r) {
                cp16(smA_u + (unsigned)nb * (ASZ * 4u) + adst[r], aptr[r]);
                cp16(smB_u + (unsigned)nb * (BSZ * 4u) + bdst[r], bptr[r]);
                aptr[r] += adv_a; bptr[r] += adv_b;
            }
        }
        CP_COMMIT();         // keep the 2-groups-in-flight invariant
        const unsigned* As = smA[cb];
        const unsigned* Bs = smB[cb];
        #pragma unroll
        for (int kk = 0; kk < 16; kk += 8) {
            unsigned af[4][4];
            const int k = kk + tg;
            #pragma unroll
            for (int mi = 0; mi < 4; ++mi) {
                int m = wm * 64 + mi * 16 + g;
                if (!AT) {
                    af[mi][0] = As[m * 20 + k];
                    af[mi][1] = As[(m + 8) * 20 + k];
                    af[mi][2] = As[m * 20 + k + 4];
                    af[mi][3] = As[(m + 8) * 20 + k + 4];
                } else {
                    af[mi][0] = As[k * 136 + m];
                    af[mi][1] = As[k * 136 + m + 8];
                    af[mi][2] = As[(k + 4) * 136 + m];
                    af[mi][3] = As[(k + 4) * 136 + m + 8];
                }
            }
            #pragma unroll
            for (int ni = 0; ni < 8; ++ni) {
                int n = wn * 64 + ni * 8 + g;
                unsigned b0, b1;
                if (!BT) { b0 = Bs[k * 136 + n]; b1 = Bs[(k + 4) * 136 + n]; }
                else     { b0 = Bs[n * 20 + k];  b1 = Bs[n * 20 + k + 4]; }
                #pragma unroll
                for (int mi = 0; mi < 4; ++mi)
                    mma8(acc[mi][ni], af[mi], b0, b1);
            }
        }
        cb = (cb == 2) ? 0 : cb + 1;
        nb = (nb == 2) ? 0 : nb + 1;
    }

    if (EPI == 2) {
        const int b = blockIdx.z;
        #pragma unroll
        for (int mi = 0; mi < 4; ++mi) {
            int row = r0 + wm * 64 + mi * 16 + g;
            #pragma unroll
            for (int rr = 0; rr < 2; ++rr) {
                int mel = row + rr * 8;
                float bb = bias[mel];
                float* op = C + ((long long)(b * 64 + (mel & 63)) * 20 + (mel >> 6)) * 2048;
                #pragma unroll
                for (int ni = 0; ni < 8; ++ni) {
                    int t = c0 + wn * 64 + ni * 8 + 2 * tg;
                    float2 v;
                    v.x = acc[mi][ni][rr * 2 + 0] + bb;
                    v.y = acc[mi][ni][rr * 2 + 1] + bb;
                    *(float2*)(op + t) = v;
                }
            }
        }
    } else {
        C += blockIdx.z * sC;
        #pragma unroll
        for (int mi = 0; mi < 4; ++mi) {
            int row = r0 + wm * 64 + mi * 16 + g;
            #pragma unroll
            for (int ni = 0; ni < 8; ++ni) {
                int col = c0 + wn * 64 + ni * 8 + 2 * tg;
                float b0v = bias ? bias[col] : 0.f;
                float b1v = bias ? bias[col + 1] : 0.f;
                float o0 = alpha * acc[mi][ni][0] + b0v;
                float o1 = alpha * acc[mi][ni][1] + b1v;
                float o2 = alpha * acc[mi][ni][2] + b0v;
                float o3 = alpha * acc[mi][ni][3] + b1v;
                float2 v0, v1;
                if (OT) {
                    v0.x = __uint_as_float(f2tf(o0));
                    v0.y = __uint_as_float(f2tf(o1));
                    v1.x = __uint_as_float(f2tf(o2));
                    v1.y = __uint_as_float(f2tf(o3));
                } else { v0.x = o0; v0.y = o1; v1.x = o2; v1.y = o3; }
                *(float2*)(C + (long long)row * ldc + col)       = v0;
                *(float2*)(C + (long long)(row + 8) * ldc + col) = v1;
            }
        }
    }
}

// -------- masked softmax, length-clamped; stores tf32-rounded weights --------
__global__ __launch_bounds__(256) void softmax_rows(float* __restrict__ att)
{
    const int row = blockIdx.x;
    const int b = row >> 11;
    float* p = att + (long long)row * 1024;
    const int len = g_len[b];
    const int lim = (len + 15) & ~15;
    const int tid = threadIdx.x;
    const int s0 = tid * 4;
    const bool act = s0 < lim;
    float4 v = make_float4(0.f, 0.f, 0.f, 0.f);
    if (act) v = ((const float4*)p)[tid];
    float vals[4] = {v.x, v.y, v.z, v.w};
    float mx = -1e30f;
    #pragma unroll
    for (int u = 0; u < 4; ++u)
        if (s0 + u < len && vals[u] > mx) mx = vals[u];
    __shared__ float red[8];
    #pragma unroll
    for (int off = 16; off > 0; off >>= 1)
        mx = fmaxf(mx, __shfl_xor_sync(0xffffffffu, mx, off));
    if ((tid & 31) == 0) red[tid >> 5] = mx;
    __syncthreads();
    mx = red[0];
    #pragma unroll
    for (int i = 1; i < 8; ++i) mx = fmaxf(mx, red[i]);
    __syncthreads();
    float sum = 0.f;
    #pragma unroll
    for (int u = 0; u < 4; ++u) {
        float e = (s0 + u < len) ? __expf(vals[u] - mx) : 0.f;
        vals[u] = e; sum += e;
    }
    #pragma unroll
    for (int off = 16; off > 0; off >>= 1)
        sum += __shfl_xor_sync(0xffffffffu, sum, off);
    if ((tid & 31) == 0) red[tid >> 5] = sum;
    __syncthreads();
    sum = 0.f;
    #pragma unroll
    for (int i = 0; i < 8; ++i) sum += red[i];
    const float inv = 1.f / sum;
    if (act) {
        v.x = __uint_as_float(f2tf(vals[0] * inv));
        v.y = __uint_as_float(f2tf(vals[1] * inv));
        v.z = __uint_as_float(f2tf(vals[2] * inv));
        v.w = __uint_as_float(f2tf(vals[3] * inv));
        ((float4*)p)[tid] = v;
    }
}

// ---------------------------------------------------------------------------
extern "C" void kernel_launch(void* const* d_in, const int* in_sizes, int n_in,
                              void* d_out, int out_size)
{
    const float* ph      = (const float*)d_in[0];
    const float* g       = (const float*)d_in[1];
    const void*  lengths = d_in[2];
    const float* Wk      = (const float*)d_in[3];
    const float* bk      = (const float*)d_in[4];
    const float* Wv      = (const float*)d_in[5];
    const float* bv      = (const float*)d_in[6];
    const float* Wq      = (const float*)d_in[7];
    const float* bq      = (const float*)d_in[8];
    const float* Wmel    = (const float*)d_in[9];
    const float* bmel    = (const float*)d_in[10];
    float* out = (float*)d_out;

    float *k_, *v_, *q_, *att_, *vmel_, *phc_, *wkc_, *wvc_, *wqc_, *wmc_;
    cudaGetSymbolAddress((void**)&k_,    g_k);
    cudaGetSymbolAddress((void**)&v_,    g_v);
    cudaGetSymbolAddress((void**)&q_,    g_q);
    cudaGetSymbolAddress((void**)&att_,  g_att);
    cudaGetSymbolAddress((void**)&vmel_, g_vmel);
    cudaGetSymbolAddress((void**)&phc_,  g_phc);
    cudaGetSymbolAddress((void**)&wkc_,  g_wkc);
    cudaGetSymbolAddress((void**)&wvc_,  g_wvc);
    cudaGetSymbolAddress((void**)&wqc_,  g_wqc);
    cudaGetSymbolAddress((void**)&wmc_,  g_wmc);

    const dim3 th(128);

    normalize_lengths<<<1, 1>>>(lengths);

    // pre-round raw inputs (except g, which the MMA truncates) to tf32 bits
    cvt_copy<<<8192, 256>>>((const float4*)ph,   (float4*)phc_, 2097152);
    cvt_copy<<<256,  256>>>((const float4*)Wk,   (float4*)wkc_, 65536);
    cvt_copy<<<256,  256>>>((const float4*)Wv,   (float4*)wvc_, 65536);
    cvt_copy<<<1280, 256>>>((const float4*)Wq,   (float4*)wqc_, 327680);
    cvt_copy<<<640,  256>>>((const float4*)Wmel, (float4*)wmc_, 163840);

    // k = ph@Wk + bk ; v = ph@Wv + bv  (skip s-blocks >= len[b])
    tc_gemm<0,0,0,1,1><<<dim3(4, 128, 1), th>>>(phc_, wkc_, bk, k_,
        512, 512, 512, 512, 0, 0, 0, 1.f);
    tc_gemm<0,0,0,1,1><<<dim3(4, 128, 1), th>>>(phc_, wvc_, bv, v_,
        512, 512, 512, 512, 0, 0, 0, 1.f);

    // q = g^T@Wq + bq  (A = g raw k-major — MMA truncates; B pre-rounded)
    tc_gemm<1,0,0,0,1><<<dim3(4, 16, 16), th>>>(g, wqc_, bq, q_,
        2560, 2048, 512, 512, 2560LL * 2048, 0, 2048LL * 512, 1.f);

    // att = scale * q@k^T  (skip CTAs with c0 >= len[b])
    tc_gemm<0,1,0,2,0><<<dim3(8, 16, 16), th>>>(q_, k_, nullptr, att_,
        512, 512, 512, 1024, 2048LL * 512, 1024LL * 512, 2048LL * 1024,
        0.04419417382415922f);

    softmax_rows<<<32768, 256>>>(att_);

    // vmel = v@Wmel  (skip s-blocks >= len[b])
    tc_gemm<0,0,0,4,1><<<dim3(10, 8, 16), th>>>(v_, wmc_, nullptr, vmel_,
        512, 512, 1280, 1280, 1024LL * 512, 0, 1024LL * 1280, 1.f);

    // out = permute(att@vmel + bmel): rows=mel (A=vmel k-major), cols=t,
    // K=S clamped to ceil(len/16)*16
    tc_gemm<1,1,2,3,0><<<dim3(16, 10, 16), th>>>(vmel_, att_, bmel, out,
        1024, 1280, 1024, 2048, 1024LL * 1280, 2048LL * 1024, 0, 1.f);
}